// round 1
// baseline (speedup 1.0000x reference)
#include <cuda_runtime.h>
#include <cstdint>

#define B_ 64
#define T_ 128
#define E_ 256
#define H_ 256          // HH
#define M_ (B_ * T_)    // 8192

// Scratch for x_proj of the current level (reused between levels)
__device__ float g_xp[M_ * H_];

// ---------------- helpers ----------------

__device__ __forceinline__ void fma2(unsigned long long &d,
                                     unsigned long long a,
                                     unsigned long long b) {
    asm("fma.rn.f32x2 %0, %1, %2, %0;" : "+l"(d) : "l"(a), "l"(b));
}

__device__ __forceinline__ unsigned long long pack2(float a, float b) {
    unsigned long long r;
    asm("mov.b64 %0, {%1, %2};" : "=l"(r) : "f"(a), "f"(b));
    return r;
}

__device__ __forceinline__ float lo32(unsigned long long v) {
    return __uint_as_float((unsigned)(v & 0xffffffffull));
}
__device__ __forceinline__ float hi32(unsigned long long v) {
    return __uint_as_float((unsigned)(v >> 32));
}

__device__ __forceinline__ float fast_tanh(float x) {
    // tanh(x) = 1 - 2/(exp(2x)+1); saturates correctly for |x| large.
    float e = __expf(2.0f * x);
    return 1.0f - __fdividef(2.0f, e + 1.0f);
}

// ---------------- x_proj GEMM ----------------
// C[m, n] = sum_k A[m, k] * Bw[n, k] + bias[n],  m in [0,8192), n,k in [0,256)
// If tokens != nullptr, A row m is Asrc[tokens[m]] (embedding gather),
// else A row m is Asrc[m] with row stride lda (reads h0 out of the output buf).
// Writes g_xp.
__global__ __launch_bounds__(256) void xp_gemm(
    const float* __restrict__ Asrc, long lda, const int* __restrict__ tokens,
    const float* __restrict__ Bw, const float* __restrict__ bias)
{
    __shared__ float As[8][128];
    __shared__ float Bs[8][128];

    const int m0 = blockIdx.x * 128;
    const int n0 = blockIdx.y * 128;
    const int tid = threadIdx.x;
    const int tx = tid & 15;       // n direction, 16 threads
    const int ty = tid >> 4;       // m direction, 16 threads
    const int lrow = tid >> 1;     // 0..127 (loader row)
    const int lc4 = (tid & 1) * 4; // 0 or 4 (loader col group)

    unsigned long long acc[8][4];
#pragma unroll
    for (int i = 0; i < 8; i++)
#pragma unroll
        for (int j = 0; j < 4; j++) acc[i][j] = 0ull;

    const float* aptr;
    {
        long ar = m0 + lrow;
        if (tokens) aptr = Asrc + (long)__ldg(tokens + ar) * lda;
        else        aptr = Asrc + ar * lda;
    }
    const float* bptr = Bw + (long)(n0 + lrow) * 256;

    for (int c = 0; c < 256; c += 8) {
        float4 av = *reinterpret_cast<const float4*>(aptr + c + lc4);
        float4 bv = *reinterpret_cast<const float4*>(bptr + c + lc4);
        __syncthreads();
        As[lc4 + 0][lrow] = av.x; As[lc4 + 1][lrow] = av.y;
        As[lc4 + 2][lrow] = av.z; As[lc4 + 3][lrow] = av.w;
        Bs[lc4 + 0][lrow] = bv.x; Bs[lc4 + 1][lrow] = bv.y;
        Bs[lc4 + 2][lrow] = bv.z; Bs[lc4 + 3][lrow] = bv.w;
        __syncthreads();
#pragma unroll
        for (int k = 0; k < 8; k++) {
            float a[8];
            *reinterpret_cast<float4*>(&a[0]) =
                *reinterpret_cast<const float4*>(&As[k][ty * 8]);
            *reinterpret_cast<float4*>(&a[4]) =
                *reinterpret_cast<const float4*>(&As[k][ty * 8 + 4]);
            const ulonglong2* bb =
                reinterpret_cast<const ulonglong2*>(&Bs[k][tx * 8]);
            ulonglong2 b01 = bb[0], b23 = bb[1];
            unsigned long long b2[4] = {b01.x, b01.y, b23.x, b23.y};
#pragma unroll
            for (int i = 0; i < 8; i++) {
                unsigned long long a2 = pack2(a[i], a[i]);
                fma2(acc[i][0], a2, b2[0]);
                fma2(acc[i][1], a2, b2[1]);
                fma2(acc[i][2], a2, b2[2]);
                fma2(acc[i][3], a2, b2[3]);
            }
        }
    }

#pragma unroll
    for (int i = 0; i < 8; i++) {
        int m = m0 + ty * 8 + i;
        float* crow = g_xp + (long)m * 256 + n0 + tx * 8;
#pragma unroll
        for (int j = 0; j < 4; j++) {
            float2 v;
            v.x = lo32(acc[i][j]) + __ldg(bias + n0 + tx * 8 + 2 * j);
            v.y = hi32(acc[i][j]) + __ldg(bias + n0 + tx * 8 + 2 * j + 1);
            *reinterpret_cast<float2*>(crow + 2 * j) = v;
        }
    }
}

// ---------------- LTC scan ----------------
// One 2-CTA cluster per batch element. Each CTA owns 128 output rows; all
// 32768 masked recurrent weights live in registers (64 packed f32x2 per
// thread). Per step: f32x2 matvec over the shared h buffer, pair reduce,
// tanh update, write own half locally + to peer SMEM, cluster barrier.
__global__ void __cluster_dims__(2, 1, 1) __launch_bounds__(256, 1) ltc_scan(
    const float* __restrict__ W_rec,
    const float* __restrict__ mask,
    const float* __restrict__ tau_raw,
    float* __restrict__ out, int col_off)
{
    // padded halves (132 floats) so even/odd lane LDS.128 hit disjoint banks
    __shared__ __align__(16) float hbuf[2][2][132];

    unsigned rank;
    asm("mov.u32 %0, %%cluster_ctarank;" : "=r"(rank));
    const unsigned peer = rank ^ 1u;
    const int b = blockIdx.x >> 1;
    const int tid = threadIdx.x;
    const int ol = tid >> 1;                 // 0..127 local output row
    const int o = ((int)rank << 7) + ol;     // global output row
    const int kh = tid & 1;                  // which 128-wide k half

    // Load masked recurrent weights for (row o, half kh) into registers.
    unsigned long long w[64];
    {
        const float2* wr =
            reinterpret_cast<const float2*>(W_rec + (long)o * 256 + kh * 128);
        const float2* mk =
            reinterpret_cast<const float2*>(mask + (long)o * 256 + kh * 128);
#pragma unroll
        for (int j = 0; j < 64; j++) {
            float2 a = __ldg(wr + j), m = __ldg(mk + j);
            w[j] = pack2(a.x * m.x, a.y * m.y);
        }
    }

    float inv_tau = 0.f, hreg = 0.f;
    if (kh == 0) {
        float tr = __ldg(tau_raw + o);
        float tau = log1pf(expf(tr)) + 0.1f;   // softplus + 0.1
        inv_tau = 1.0f / tau;
    }

    // h(0) = 0
    hbuf[0][tid >> 7][tid & 127] = 0.0f;
    __syncthreads();

    const float* xpp = g_xp + ((long)b * T_) * H_ + o;
    float* outp = out + ((long)b * T_) * 512 + col_off + o;

    for (int t = 0; t < T_; ++t) {
        const int cur = t & 1;
        const ulonglong2* hp =
            reinterpret_cast<const ulonglong2*>(&hbuf[cur][kh][0]);

        unsigned long long a0 = 0ull, a1 = 0ull, a2 = 0ull, a3 = 0ull;
#pragma unroll
        for (int j = 0; j < 32; j += 2) {
            ulonglong2 x0 = hp[j];
            ulonglong2 x1 = hp[j + 1];
            fma2(a0, w[2 * j + 0], x0.x);
            fma2(a1, w[2 * j + 1], x0.y);
            fma2(a2, w[2 * j + 2], x1.x);
            fma2(a3, w[2 * j + 3], x1.y);
        }
        float s = ((lo32(a0) + hi32(a0)) + (lo32(a1) + hi32(a1))) +
                  ((lo32(a2) + hi32(a2)) + (lo32(a3) + hi32(a3)));
        s += __shfl_xor_sync(0xffffffffu, s, 1);

        if (kh == 0) {
            float pre = s + xpp[(long)t * H_];
            float hn = fmaf(fast_tanh(pre) - hreg, inv_tau, hreg);
            hreg = hn;
            outp[(long)t * 512] = hn;
            // own half into next buffer, locally and in the peer CTA
            hbuf[cur ^ 1][rank][ol] = hn;
            unsigned laddr =
                (unsigned)__cvta_generic_to_shared(&hbuf[cur ^ 1][rank][ol]);
            unsigned raddr;
            asm("mapa.shared::cluster.u32 %0, %1, %2;"
                : "=r"(raddr) : "r"(laddr), "r"(peer));
            asm volatile("st.shared::cluster.f32 [%0], %1;"
                         :: "r"(raddr), "f"(hn) : "memory");
        }
        // release own stores / acquire peer's; also keeps peer alive until
        // the last remote store has landed.
        asm volatile("barrier.cluster.arrive.aligned;" ::: "memory");
        asm volatile("barrier.cluster.wait.aligned;" ::: "memory");
    }
}

// ---------------- launcher ----------------

extern "C" void kernel_launch(void* const* d_in, const int* in_sizes, int n_in,
                              void* d_out, int out_size) {
    const int*   tokens = (const int*)  d_in[0];
    const float* emb    = (const float*)d_in[1];
    const float* W_in0  = (const float*)d_in[2];
    const float* W_rec0 = (const float*)d_in[3];
    const float* b0     = (const float*)d_in[4];
    const float* tau0   = (const float*)d_in[5];
    const float* mask0  = (const float*)d_in[6];
    const float* W_in1  = (const float*)d_in[7];
    const float* W_rec1 = (const float*)d_in[8];
    const float* b1     = (const float*)d_in[9];
    const float* tau1   = (const float*)d_in[10];
    const float* mask1  = (const float*)d_in[11];
    float* out = (float*)d_out;

    dim3 gemm_grid(M_ / 128, 2);

    // level 0: xp0 = gather(emb, tokens) @ W_in0^T + b0 ; scan -> out[:, :, 0:256]
    xp_gemm<<<gemm_grid, 256>>>(emb, E_, tokens, W_in0, b0);
    ltc_scan<<<2 * B_, 256>>>(W_rec0, mask0, tau0, out, 0);

    // level 1: xp1 = h0_seq @ W_in1^T + b1 ; scan -> out[:, :, 256:512]
    xp_gemm<<<gemm_grid, 256>>>(out, 512, nullptr, W_in1, b1);
    ltc_scan<<<2 * B_, 256>>>(W_rec1, mask1, tau1, out, 256);
}

// round 2
// speedup vs baseline: 1.2379x; 1.2379x over previous
#include <cuda_runtime.h>
#include <cstdint>

#define B_ 64
#define T_ 128
#define E_ 256
#define H_ 256          // HH
#define M_ (B_ * T_)    // 8192

// Scratch for x_proj of the current level (reused between levels)
__device__ float g_xp[M_ * H_];

// ---------------- helpers ----------------

__device__ __forceinline__ void fma2(unsigned long long &d,
                                     unsigned long long a,
                                     unsigned long long b) {
    asm("fma.rn.f32x2 %0, %1, %2, %0;" : "+l"(d) : "l"(a), "l"(b));
}

__device__ __forceinline__ unsigned long long pack2(float a, float b) {
    unsigned long long r;
    asm("mov.b64 %0, {%1, %2};" : "=l"(r) : "f"(a), "f"(b));
    return r;
}

__device__ __forceinline__ float lo32(unsigned long long v) {
    return __uint_as_float((unsigned)(v & 0xffffffffull));
}
__device__ __forceinline__ float hi32(unsigned long long v) {
    return __uint_as_float((unsigned)(v >> 32));
}

__device__ __forceinline__ float fast_tanh(float x) {
    float e = __expf(2.0f * x);
    return 1.0f - __fdividef(2.0f, e + 1.0f);
}

__device__ __forceinline__ unsigned smem_u32(const void* p) {
    unsigned a;
    asm("{ .reg .u64 t; cvta.to.shared.u64 t, %1; cvt.u32.u64 %0, t; }"
        : "=r"(a) : "l"(p));
    return a;
}

__device__ __forceinline__ unsigned mapa_rank(unsigned laddr, unsigned rank) {
    unsigned r;
    asm("mapa.shared::cluster.u32 %0, %1, %2;" : "=r"(r) : "r"(laddr), "r"(rank));
    return r;
}

__device__ __forceinline__ void mbar_init(unsigned addr, unsigned cnt) {
    asm volatile("mbarrier.init.shared.b64 [%0], %1;" :: "r"(addr), "r"(cnt) : "memory");
}

__device__ __forceinline__ void mbar_inval(unsigned addr) {
    asm volatile("mbarrier.inval.shared.b64 [%0];" :: "r"(addr) : "memory");
}

__device__ __forceinline__ void mbar_expect_tx(unsigned addr, unsigned bytes) {
    asm volatile("mbarrier.arrive.expect_tx.shared.b64 _, [%0], %1;"
                 :: "r"(addr), "r"(bytes) : "memory");
}

__device__ __forceinline__ void st_async_f32(unsigned daddr, float v, unsigned mbar) {
    asm volatile(
        "st.async.shared::cluster.mbarrier::complete_tx::bytes.f32 [%0], %1, [%2];"
        :: "r"(daddr), "f"(v), "r"(mbar) : "memory");
}

__device__ __forceinline__ void mbar_wait_parity(unsigned addr, unsigned parity) {
    unsigned done;
    asm volatile(
        "{\n\t.reg .pred p;\n\t"
        "mbarrier.try_wait.parity.acquire.cta.shared::cta.b64 p, [%1], %2;\n\t"
        "selp.b32 %0, 1, 0, p;\n\t}"
        : "=r"(done) : "r"(addr), "r"(parity) : "memory");
    if (!done) {
        asm volatile(
            "{\n\t.reg .pred P1;\n\t"
            "WL_%=:\n\t"
            "mbarrier.try_wait.parity.acquire.cta.shared::cta.b64 P1, [%0], %1, 0x989680;\n\t"
            "@P1 bra.uni WD_%=;\n\t"
            "bra.uni WL_%=;\n\t"
            "WD_%=:\n\t}"
            :: "r"(addr), "r"(parity) : "memory");
    }
}

// ---------------- x_proj GEMM ----------------
__global__ __launch_bounds__(256) void xp_gemm(
    const float* __restrict__ Asrc, long lda, const int* __restrict__ tokens,
    const float* __restrict__ Bw, const float* __restrict__ bias)
{
    __shared__ float As[8][128];
    __shared__ float Bs[8][128];

    const int m0 = blockIdx.x * 128;
    const int n0 = blockIdx.y * 128;
    const int tid = threadIdx.x;
    const int tx = tid & 15;
    const int ty = tid >> 4;
    const int lrow = tid >> 1;
    const int lc4 = (tid & 1) * 4;

    unsigned long long acc[8][4];
#pragma unroll
    for (int i = 0; i < 8; i++)
#pragma unroll
        for (int j = 0; j < 4; j++) acc[i][j] = 0ull;

    const float* aptr;
    {
        long ar = m0 + lrow;
        if (tokens) aptr = Asrc + (long)__ldg(tokens + ar) * lda;
        else        aptr = Asrc + ar * lda;
    }
    const float* bptr = Bw + (long)(n0 + lrow) * 256;

    for (int c = 0; c < 256; c += 8) {
        float4 av = *reinterpret_cast<const float4*>(aptr + c + lc4);
        float4 bv = *reinterpret_cast<const float4*>(bptr + c + lc4);
        __syncthreads();
        As[lc4 + 0][lrow] = av.x; As[lc4 + 1][lrow] = av.y;
        As[lc4 + 2][lrow] = av.z; As[lc4 + 3][lrow] = av.w;
        Bs[lc4 + 0][lrow] = bv.x; Bs[lc4 + 1][lrow] = bv.y;
        Bs[lc4 + 2][lrow] = bv.z; Bs[lc4 + 3][lrow] = bv.w;
        __syncthreads();
#pragma unroll
        for (int k = 0; k < 8; k++) {
            float a[8];
            *reinterpret_cast<float4*>(&a[0]) =
                *reinterpret_cast<const float4*>(&As[k][ty * 8]);
            *reinterpret_cast<float4*>(&a[4]) =
                *reinterpret_cast<const float4*>(&As[k][ty * 8 + 4]);
            const ulonglong2* bb =
                reinterpret_cast<const ulonglong2*>(&Bs[k][tx * 8]);
            ulonglong2 b01 = bb[0], b23 = bb[1];
            unsigned long long b2[4] = {b01.x, b01.y, b23.x, b23.y};
#pragma unroll
            for (int i = 0; i < 8; i++) {
                unsigned long long a2 = pack2(a[i], a[i]);
                fma2(acc[i][0], a2, b2[0]);
                fma2(acc[i][1], a2, b2[1]);
                fma2(acc[i][2], a2, b2[2]);
                fma2(acc[i][3], a2, b2[3]);
            }
        }
    }

#pragma unroll
    for (int i = 0; i < 8; i++) {
        int m = m0 + ty * 8 + i;
        float* crow = g_xp + (long)m * 256 + n0 + tx * 8;
#pragma unroll
        for (int j = 0; j < 4; j++) {
            float2 v;
            v.x = lo32(acc[i][j]) + __ldg(bias + n0 + tx * 8 + 2 * j);
            v.y = hi32(acc[i][j]) + __ldg(bias + n0 + tx * 8 + 2 * j + 1);
            *reinterpret_cast<float2*>(crow + 2 * j) = v;
        }
    }
}

// ---------------- LTC scan ----------------
// One 2-CTA cluster per batch element. Weights register-resident as before.
// Per-step sync: st.async + mbarrier transaction counts instead of the
// (expensive) hardware cluster barrier. Double-buffered h; mbar[buf] expects
// 1 arrival + 1024 tx bytes per phase (128 floats from each CTA's writers,
// delivered to BOTH CTAs via st.async).
__global__ void __cluster_dims__(2, 1, 1) __launch_bounds__(256, 1) ltc_scan(
    const float* __restrict__ W_rec,
    const float* __restrict__ mask,
    const float* __restrict__ tau_raw,
    float* __restrict__ out, int col_off)
{
    __shared__ __align__(16) float hbuf[2][2][132];
    __shared__ __align__(8) unsigned long long mbar[2];

    unsigned rank;
    asm("mov.u32 %0, %%cluster_ctarank;" : "=r"(rank));
    const int b = blockIdx.x >> 1;
    const int tid = threadIdx.x;
    const int ol = tid >> 1;                 // 0..127 local output row
    const int o = ((int)rank << 7) + ol;     // global output row
    const int kh = tid & 1;                  // which 128-wide k half

    // Load masked recurrent weights for (row o, half kh) into registers.
    unsigned long long w[64];
    {
        const float2* wr =
            reinterpret_cast<const float2*>(W_rec + (long)o * 256 + kh * 128);
        const float2* mk =
            reinterpret_cast<const float2*>(mask + (long)o * 256 + kh * 128);
#pragma unroll
        for (int j = 0; j < 64; j++) {
            float2 a = __ldg(wr + j), m = __ldg(mk + j);
            w[j] = pack2(a.x * m.x, a.y * m.y);
        }
    }

    float inv_tau = 0.f, hreg = 0.f;
    if (kh == 0) {
        float tr = __ldg(tau_raw + o);
        float tau = log1pf(expf(tr)) + 0.1f;   // softplus + 0.1
        inv_tau = 1.0f / tau;
    }

    // h(0) = 0 (both halves, local)
    hbuf[0][tid >> 7][tid & 127] = 0.0f;

    if (tid == 0) {
        mbar_init(smem_u32(&mbar[0]), 1);
        mbar_init(smem_u32(&mbar[1]), 1);
        // phase0 of mbar[1]: completed by step-0 writes, consumed at step 1
        mbar_expect_tx(smem_u32(&mbar[1]), 1024);
    }
    // one-time cluster rendezvous: peer's mbarrier init + expect visible
    // before any st.async targets it; also covers hbuf[0] zeroing order.
    asm volatile("barrier.cluster.arrive.aligned;" ::: "memory");
    asm volatile("barrier.cluster.wait.aligned;" ::: "memory");

    // Destination addresses (this thread's slot in both CTAs, both buffers)
    unsigned dAddr[2][2], mAddr[2][2];   // [buf][target_rank]
#pragma unroll
    for (int bf = 0; bf < 2; bf++) {
        unsigned ld = smem_u32(&hbuf[bf][rank][ol]);
        unsigned lm = smem_u32(&mbar[bf]);
#pragma unroll
        for (int r = 0; r < 2; r++) {
            dAddr[bf][r] = mapa_rank(ld, r);
            mAddr[bf][r] = mapa_rank(lm, r);
        }
    }
    const unsigned lmb0 = smem_u32(&mbar[0]);
    const unsigned lmb1 = smem_u32(&mbar[1]);

    const float* xpp = g_xp + ((long)b * T_) * H_ + o;
    float* outp = out + ((long)b * T_) * 512 + col_off + o;

    for (int t = 0; t < T_; ++t) {
        const int cur = t & 1;

        if (t > 0) {
            unsigned parity = ((unsigned)(t >> 1) + 1u - (unsigned)cur) & 1u;
            mbar_wait_parity(cur ? lmb1 : lmb0, parity);
        }

        const ulonglong2* hp =
            reinterpret_cast<const ulonglong2*>(&hbuf[cur][kh][0]);

        unsigned long long a0 = 0ull, a1 = 0ull, a2 = 0ull, a3 = 0ull;
#pragma unroll
        for (int j = 0; j < 32; j += 2) {
            ulonglong2 x0 = hp[j];
            ulonglong2 x1 = hp[j + 1];
            fma2(a0, w[2 * j + 0], x0.x);
            fma2(a1, w[2 * j + 1], x0.y);
            fma2(a2, w[2 * j + 2], x1.x);
            fma2(a3, w[2 * j + 3], x1.y);
        }
        float s = ((lo32(a0) + hi32(a0)) + (lo32(a1) + hi32(a1))) +
                  ((lo32(a2) + hi32(a2)) + (lo32(a3) + hi32(a3)));
        s += __shfl_xor_sync(0xffffffffu, s, 1);

        // Arm the next phase of mbar[cur] (consumed at step t+2). Must be
        // before this step's st.async batch (ordered by the barrier below +
        // the causal chain through the peer's wait).
        if (tid == 0 && t + 2 < T_) {
            mbar_expect_tx(cur ? lmb1 : lmb0, 1024);
        }
        // WAR: all threads have finished reading hbuf[nxt] (step t-1) before
        // any thread overwrites it below.
        __syncthreads();

        if (kh == 0) {
            float pre = s + xpp[(long)t * H_];
            float hn = fmaf(fast_tanh(pre) - hreg, inv_tau, hreg);
            hreg = hn;
            outp[(long)t * 512] = hn;
            if (t + 1 < T_) {
                const int nxt = cur ^ 1;
                // publish to both CTAs; tx counts complete the readers' wait
                st_async_f32(dAddr[nxt][0], hn, mAddr[nxt][0]);
                st_async_f32(dAddr[nxt][1], hn, mAddr[nxt][1]);
            }
        }
    }

    __syncthreads();
    if (tid == 0) {
        mbar_inval(lmb0);
        mbar_inval(lmb1);
    }
}

// ---------------- launcher ----------------

extern "C" void kernel_launch(void* const* d_in, const int* in_sizes, int n_in,
                              void* d_out, int out_size) {
    const int*   tokens = (const int*)  d_in[0];
    const float* emb    = (const float*)d_in[1];
    const float* W_in0  = (const float*)d_in[2];
    const float* W_rec0 = (const float*)d_in[3];
    const float* b0     = (const float*)d_in[4];
    const float* tau0   = (const float*)d_in[5];
    const float* mask0  = (const float*)d_in[6];
    const float* W_in1  = (const float*)d_in[7];
    const float* W_rec1 = (const float*)d_in[8];
    const float* b1     = (const float*)d_in[9];
    const float* tau1   = (const float*)d_in[10];
    const float* mask1  = (const float*)d_in[11];
    float* out = (float*)d_out;

    dim3 gemm_grid(M_ / 128, 2);

    // level 0
    xp_gemm<<<gemm_grid, 256>>>(emb, E_, tokens, W_in0, b0);
    ltc_scan<<<2 * B_, 256>>>(W_rec0, mask0, tau0, out, 0);

    // level 1
    xp_gemm<<<gemm_grid, 256>>>(out, 512, nullptr, W_in1, b1);
    ltc_scan<<<2 * B_, 256>>>(W_rec1, mask1, tau1, out, 256);
}